// round 17
// baseline (speedup 1.0000x reference)
#include <cuda_runtime.h>
#include <cuda_fp16.h>
#include <cstdint>

// Problem constants
#define DM   1024
#define NH   16
#define HD   64
#define BB   2
#define TT   2048

// Scratch (device globals: allocation-free rule). 16B-aligned for vector/cp.async.
// g_qkv: Q,K regions [w][b][h][t][d]; V region stored TRANSPOSED [b][h][d][t].
__device__ __align__(16) __half g_qkv[3 * BB * NH * TT * HD];
__device__ __align__(16) __half g_att[BB * TT * DM];    // [b][t][h][d]
__device__ __align__(16) __half g_xr[BB * TT * DM];     // x rounded
__device__ __align__(16) __half g_wqT[3 * DM * DM];     // w_qkv^T  [n][k]
__device__ __align__(16) __half g_wpT[DM * DM];         // w_proj^T [n][k]

// ---------------------------------------------------------------------------
// helpers
// ---------------------------------------------------------------------------
__device__ __forceinline__ float ex2(float x) {
    float r;
    asm("ex2.approx.f32 %0, %1;" : "=f"(r) : "f"(x));
    return r;
}

__device__ __forceinline__ void mma_f16(float& c0, float& c1, float& c2, float& c3,
                                        uint32_t a0, uint32_t a1, uint32_t a2, uint32_t a3,
                                        uint32_t b0, uint32_t b1) {
    asm volatile(
        "mma.sync.aligned.m16n8k16.row.col.f32.f16.f16.f32 "
        "{%0,%1,%2,%3}, {%4,%5,%6,%7}, {%8,%9}, {%0,%1,%2,%3};"
        : "+f"(c0), "+f"(c1), "+f"(c2), "+f"(c3)
        : "r"(a0), "r"(a1), "r"(a2), "r"(a3), "r"(b0), "r"(b1));
}

__device__ __forceinline__ void ldsm4(uint32_t& r0, uint32_t& r1,
                                      uint32_t& r2, uint32_t& r3, uint32_t addr) {
    asm volatile("ldmatrix.sync.aligned.m8n8.x4.shared.b16 {%0,%1,%2,%3}, [%4];"
                 : "=r"(r0), "=r"(r1), "=r"(r2), "=r"(r3) : "r"(addr));
}

__device__ __forceinline__ uint32_t smem_u32(const void* p) {
    uint32_t a;
    asm("{ .reg .u64 t; cvta.to.shared.u64 t, %1; cvt.u32.u64 %0, t; }"
        : "=r"(a) : "l"(p));
    return a;
}
__device__ __forceinline__ void cpa16(uint32_t saddr, const void* g) {
    asm volatile("cp.async.cg.shared.global [%0], [%1], 16;"
                 :: "r"(saddr), "l"(g) : "memory");
}
#define CP_COMMIT() asm volatile("cp.async.commit_group;" ::: "memory")
#define CP_WAIT1()  asm volatile("cp.async.wait_group 1;" ::: "memory")
#define CP_WAIT0()  asm volatile("cp.async.wait_group 0;" ::: "memory")

__device__ __forceinline__ uint32_t pack_h2(float a, float b) {
    __half2 h = __floats2half2_rn(a, b);
    return *(uint32_t*)&h;
}

// ---------------------------------------------------------------------------
// Prepass 1: round x -> half
// ---------------------------------------------------------------------------
__global__ __launch_bounds__(256) void round_x_k(const float* __restrict__ x)
{
    const int n8 = BB * TT * DM / 8;
    const int stride = gridDim.x * blockDim.x;
    for (int i = blockIdx.x * blockDim.x + threadIdx.x; i < n8; i += stride) {
        float4 a = *(const float4*)(x + (size_t)i * 8);
        float4 b = *(const float4*)(x + (size_t)i * 8 + 4);
        uint4 o = { pack_h2(a.x, a.y), pack_h2(a.z, a.w),
                    pack_h2(b.x, b.y), pack_h2(b.z, b.w) };
        *(uint4*)((__half*)g_xr + (size_t)i * 8) = o;
    }
}

// ---------------------------------------------------------------------------
// Prepass 2: transpose + round BOTH weights in one launch.
// grid.x tiles: [0,96) -> w_qkv (C=3072), [96,128) -> w_proj (C=1024).
// ---------------------------------------------------------------------------
__global__ __launch_bounds__(256) void transpose_both(const float* __restrict__ wq,
                                                      const float* __restrict__ wp)
{
    __shared__ float tbuf[32][33];
    const int R = DM;
    const float* src;
    __half* dst;
    int C, bx;
    if (blockIdx.x < 96) { src = wq; dst = (__half*)g_wqT; C = 3 * DM; bx = blockIdx.x * 32; }
    else                 { src = wp; dst = (__half*)g_wpT; C = DM; bx = (blockIdx.x - 96) * 32; }
    const int by = blockIdx.y * 32;
    const int tx = threadIdx.x, ty = threadIdx.y;
#pragma unroll
    for (int i = 0; i < 32; i += 8)
        tbuf[ty + i][tx] = src[(size_t)(by + ty + i) * C + bx + tx];
    __syncthreads();
#pragma unroll
    for (int i = 0; i < 32; i += 8)
        dst[(size_t)(bx + ty + i) * R + by + tx] = __float2half_rn(tbuf[tx][ty + i]);
}

// ---------------------------------------------------------------------------
// fp16 tensor-core GEMM (m16n8k16), 256x128 CTA tile, 512 threads (16 warps,
// warp tile 64x32), BK=64, 3-stage cp.async, ldmatrix frags.
// A stage [256][72], B stage [128][72].  1 CTA/SM (full RF + 162KB smem).
// MODE 0: A=g_xr; epilogue -> g_qkv (Q prescaled, V transposed).
// MODE 1: A=g_att; epilogue -> fp32 C.
// ---------------------------------------------------------------------------
#define AS_H (256 * 72)
#define BS_H (128 * 72)
#define GSMEM_BYTES (3 * (AS_H + BS_H) * 2)   // 165888 B

#define QSCALE 0.18033688011112042f   // 0.125 * log2(e)

template <int MODE>
__global__ __launch_bounds__(512, 1) void mma_gemm(const float* __restrict__ bias,
                                                   float* __restrict__ Cout,
                                                   int M, int N, int K)
{
    extern __shared__ char smraw[];
    __half* AsF = (__half*)smraw;
    __half* BsF = AsF + 3 * AS_H;
    const uint32_t abase = smem_u32(AsF);
    const uint32_t bbase = smem_u32(BsF);

    const int tid  = threadIdx.x;
    const int bm   = blockIdx.y * 256;
    const int bn   = blockIdx.x * 128;
    const int w    = tid >> 5;
    const int lane = tid & 31;
    const int g    = lane >> 2;
    const int t    = lane & 3;
    const int m0   = (w & 3) * 64;     // warp m offset (4 m-groups)
    const int n0   = (w >> 2) * 32;    // warp n offset (4 n-groups)

    // ldmatrix per-lane offsets
    const int a_r = lane & 15;
    const int a_c = (lane >> 4) * 8;
    const int b_r = ((lane >> 4) << 3) + (lane & 7);
    const int b_c = ((lane >> 3) & 1) * 8;

    const __half* Aeff = (MODE == 0) ? (const __half*)g_xr : (const __half*)g_att;
    const __half* Bt   = (MODE == 0) ? (const __half*)g_wqT : (const __half*)g_wpT;

    float acc[4][4][4];
#pragma unroll
    for (int mf = 0; mf < 4; mf++)
#pragma unroll
        for (int nt = 0; nt < 4; nt++)
#pragma unroll
            for (int r = 0; r < 4; r++) acc[mf][nt][r] = 0.f;

    // cp.async indexing: A chunk 256x64 = 2048 f4 (4/thread); B 128x64 = 1024 (2/thread)
    int arow[4], acol[4], brow[2], bcol[2];
#pragma unroll
    for (int j = 0; j < 4; j++) {
        const int f = tid + 512 * j;
        arow[j] = f >> 3;  acol[j] = (f & 7) * 8;
    }
#pragma unroll
    for (int j = 0; j < 2; j++) {
        const int f = tid + 512 * j;
        brow[j] = f >> 3;  bcol[j] = (f & 7) * 8;
    }

    const int NC = K >> 6;   // 16

    auto issue = [&](int c) {
        const int s = c % 3;
        const int k0 = c << 6;
#pragma unroll
        for (int j = 0; j < 4; j++)
            cpa16(abase + (uint32_t)(s * AS_H + arow[j] * 72 + acol[j]) * 2u,
                  Aeff + (size_t)(bm + arow[j]) * K + k0 + acol[j]);
#pragma unroll
        for (int j = 0; j < 2; j++)
            cpa16(bbase + (uint32_t)(s * BS_H + brow[j] * 72 + bcol[j]) * 2u,
                  Bt + (size_t)(bn + brow[j]) * K + k0 + bcol[j]);
    };

    issue(0); CP_COMMIT();
    issue(1); CP_COMMIT();

    for (int c = 0; c < NC; c++) {
        const int st = c % 3;
        CP_WAIT1();
        __syncthreads();

        if (c + 2 < NC) issue(c + 2);
        CP_COMMIT();

        const uint32_t as = abase + (uint32_t)(st * AS_H) * 2u;
        const uint32_t bs = bbase + (uint32_t)(st * BS_H) * 2u;
#pragma unroll
        for (int ks = 0; ks < 4; ks++) {
            const int kb = ks * 16;
            uint32_t af[4][4], bf[4][2];
#pragma unroll
            for (int mf = 0; mf < 4; mf++)
                ldsm4(af[mf][0], af[mf][1], af[mf][2], af[mf][3],
                      as + (uint32_t)((m0 + mf * 16 + a_r) * 72 + kb + a_c) * 2u);
#pragma unroll
            for (int p = 0; p < 2; p++)
                ldsm4(bf[2 * p][0], bf[2 * p][1], bf[2 * p + 1][0], bf[2 * p + 1][1],
                      bs + (uint32_t)((n0 + p * 16 + b_r) * 72 + kb + b_c) * 2u);
#pragma unroll
            for (int mf = 0; mf < 4; mf++)
#pragma unroll
                for (int nt = 0; nt < 4; nt++)
                    mma_f16(acc[mf][nt][0], acc[mf][nt][1],
                            acc[mf][nt][2], acc[mf][nt][3],
                            af[mf][0], af[mf][1], af[mf][2], af[mf][3],
                            bf[nt][0], bf[nt][1]);
        }
    }

    const int ng = bn + n0;   // 32-aligned warp n base
    if (MODE == 0) {
        const int which = ng >> 10;
        const int rem   = ng & 1023;
        const int h     = rem >> 6;
        const int d0    = rem & 63;    // 0 or 32
#pragma unroll
        for (int mf = 0; mf < 4; mf++) {
            const int row0 = bm + m0 + mf * 16 + g;
            const int row1 = row0 + 8;
            const int b0i = row0 >> 11, t0i = row0 & 2047;
            const int b1i = row1 >> 11, t1i = row1 & 2047;
            if (which < 2) {
                __half* base0 = (__half*)g_qkv
                    + ((size_t)((which * BB + b0i) * NH + h) * TT + t0i) * HD;
                __half* base1 = (__half*)g_qkv
                    + ((size_t)((which * BB + b1i) * NH + h) * TT + t1i) * HD;
                const float sc = (which == 0) ? QSCALE : 1.0f;
#pragma unroll
                for (int nt = 0; nt < 4; nt++) {
                    const int d = d0 + nt * 8 + 2 * t;
                    const float bx = bias[ng + nt * 8 + 2 * t];
                    const float by = bias[ng + nt * 8 + 2 * t + 1];
                    *(uint32_t*)&base0[d] = pack_h2((acc[mf][nt][0] + bx) * sc,
                                                    (acc[mf][nt][1] + by) * sc);
                    *(uint32_t*)&base1[d] = pack_h2((acc[mf][nt][2] + bx) * sc,
                                                    (acc[mf][nt][3] + by) * sc);
                }
            } else {
                __half* vb0 = (__half*)g_qkv
                    + (size_t)((2 * BB + b0i) * NH + h) * HD * TT;
                __half* vb1 = (__half*)g_qkv
                    + (size_t)((2 * BB + b1i) * NH + h) * HD * TT;
#pragma unroll
                for (int nt = 0; nt < 4; nt++) {
                    const int d = d0 + nt * 8 + 2 * t;
                    const float bx = bias[ng + nt * 8 + 2 * t];
                    const float by = bias[ng + nt * 8 + 2 * t + 1];
                    vb0[(size_t)d * TT + t0i]       = __float2half_rn(acc[mf][nt][0] + bx);
                    vb0[(size_t)(d + 1) * TT + t0i] = __float2half_rn(acc[mf][nt][1] + by);
                    vb1[(size_t)d * TT + t1i]       = __float2half_rn(acc[mf][nt][2] + bx);
                    vb1[(size_t)(d + 1) * TT + t1i] = __float2half_rn(acc[mf][nt][3] + by);
                }
            }
        }
    } else {
#pragma unroll
        for (int mf = 0; mf < 4; mf++) {
            const int row0 = bm + m0 + mf * 16 + g;
            const int row1 = row0 + 8;
#pragma unroll
            for (int nt = 0; nt < 4; nt++) {
                const int n = ng + nt * 8 + 2 * t;
                const float bx = bias[n], by = bias[n + 1];
                float2 o0 = { acc[mf][nt][0] + bx, acc[mf][nt][1] + by };
                float2 o1 = { acc[mf][nt][2] + bx, acc[mf][nt][3] + by };
                *(float2*)(Cout + (size_t)row0 * N + n) = o0;
                *(float2*)(Cout + (size_t)row1 * N + n) = o1;
            }
        }
    }
}

// ---------------------------------------------------------------------------
// Flash attention, fp16 m16n8k16 + ldmatrix, fp32 softmax (exp2 domain),
// 2-stage cp.async K/V, warp-level causal skip, heavy CTAs first.
// K consumed [s][d]; V consumed transposed [d][t] (written by GEMM).
// (unchanged from R16 best)
// ---------------------------------------------------------------------------
#define FK_H (64 * 72)
#define FV_H (64 * 72)
#define FQ_H (128 * 72)
#define FLASH_SMEM ((2 * FK_H + 2 * FV_H + FQ_H) * 2)   // 55296 B

__global__ __launch_bounds__(256, 2) void flash_mma()
{
    extern __shared__ char smraw[];
    __half* Kb = (__half*)smraw;
    __half* Vb = Kb + 2 * FK_H;
    __half* Ps = Vb + 2 * FV_H;
    const uint32_t kmb = smem_u32(Kb);
    const uint32_t vmb = smem_u32(Vb);
    const uint32_t pmb = smem_u32(Ps);

    const int tid  = threadIdx.x;
    const int w    = tid >> 5;
    const int lane = tid & 31;
    const int g    = lane >> 2;
    const int t    = lane & 3;
    const int qt   = (int)gridDim.x - 1 - (int)blockIdx.x;
    const int h    = blockIdx.y;
    const int b    = blockIdx.z;
    const int q_base = qt * 128;
    const int mb     = w * 16;

    const int a_r = lane & 15;
    const int a_c = (lane >> 4) * 8;
    const int b_r = ((lane >> 4) << 3) + (lane & 7);
    const int b_c = ((lane >> 3) & 1) * 8;

    const __half* Qg = (const __half*)g_qkv + (size_t)((0 * BB + b) * NH + h) * TT * HD;
    const __half* Kg = (const __half*)g_qkv + (size_t)((1 * BB + b) * NH + h) * TT * HD;
    const __half* Vt = (const __half*)g_qkv + (size_t)((2 * BB + b) * NH + h) * HD * TT;

    auto issue_kv = [&](int kt) {
        const int s = kt & 1;
#pragma unroll
        for (int j = 0; j < 2; j++) {
            const int v = tid + 256 * j;
            const int row = v >> 3;
            const int c8  = (v & 7) * 8;
            cpa16(kmb + (uint32_t)(s * FK_H + row * 72 + c8) * 2u,
                  Kg + (size_t)(kt * 64 + row) * HD + c8);
            cpa16(vmb + (uint32_t)(s * FV_H + row * 72 + c8) * 2u,
                  Vt + (size_t)row * TT + kt * 64 + c8);
        }
    };

    // stage Q (pure copy: already half + prescaled by GEMM epilogue)
#pragma unroll
    for (int j = 0; j < 4; j++) {
        const int v = tid + 256 * j;
        const int row = v >> 3;
        const int c8  = (v & 7) * 8;
        cpa16(pmb + (uint32_t)(row * 72 + c8) * 2u,
              Qg + (size_t)(q_base + row) * HD + c8);
    }
    issue_kv(0);
    CP_COMMIT();
    CP_WAIT0();
    __syncthreads();

    uint32_t qa[4][4];
#pragma unroll
    for (int ks = 0; ks < 4; ks++)
        ldsm4(qa[ks][0], qa[ks][1], qa[ks][2], qa[ks][3],
              pmb + (uint32_t)((mb + a_r) * 72 + ks * 16 + a_c) * 2u);

    float oacc[8][4];
#pragma unroll
    for (int nt = 0; nt < 8; nt++)
#pragma unroll
        for (int r = 0; r < 4; r++) oacc[nt][r] = 0.f;
    float m0 = -1e30f, m1 = -1e30f, l0 = 0.f, l1 = 0.f;
    const int r0 = q_base + mb + g, r1 = r0 + 8;

    const int nkt = 2 * qt + 2;
    for (int kt = 0; kt < nkt; kt++) {
        const int st = kt & 1;
        const uint32_t ks_b = kmb + (uint32_t)(st * FK_H) * 2u;
        const uint32_t vs_b = vmb + (uint32_t)(st * FV_H) * 2u;

        CP_WAIT0();
        __syncthreads();   // tile kt visible; all warps done with stage st^1

        if (kt + 1 < nkt) issue_kv(kt + 1);
        CP_COMMIT();

        // warp-level causal skip (bit-exact: tile fully masked for this warp)
        if (kt * 64 > q_base + mb + 15) continue;

        // S = Q @ K^T   (16x64 per warp)
        float sacc[8][4];
#pragma unroll
        for (int nt = 0; nt < 8; nt++)
#pragma unroll
            for (int r = 0; r < 4; r++) sacc[nt][r] = 0.f;
#pragma unroll
        for (int ks = 0; ks < 4; ks++) {
            const int kb = ks * 16;
            uint32_t bf[8][2];
#pragma unroll
            for (int p = 0; p < 4; p++)
                ldsm4(bf[2 * p][0], bf[2 * p][1], bf[2 * p + 1][0], bf[2 * p + 1][1],
                      ks_b + (uint32_t)((p * 16 + b_r) * 72 + kb + b_c) * 2u);
#pragma unroll
            for (int nt = 0; nt < 8; nt++)
                mma_f16(sacc[nt][0], sacc[nt][1], sacc[nt][2], sacc[nt][3],
                        qa[ks][0], qa[ks][1], qa[ks][2], qa[ks][3],
                        bf[nt][0], bf[nt][1]);
        }

        if (kt >= 2 * qt) {
            const int sb = kt * 64;
#pragma unroll
            for (int nt = 0; nt < 8; nt++) {
                const int c0 = sb + nt * 8 + 2 * t, c1 = c0 + 1;
                if (c0 > r0) sacc[nt][0] = -1e30f;
                if (c1 > r0) sacc[nt][1] = -1e30f;
                if (c0 > r1) sacc[nt][2] = -1e30f;
                if (c1 > r1) sacc[nt][3] = -1e30f;
            }
        }

        float mx0 = -1e30f, mx1 = -1e30f;
#pragma unroll
        for (int nt = 0; nt < 8; nt++) {
            mx0 = fmaxf(mx0, fmaxf(sacc[nt][0], sacc[nt][1]));
            mx1 = fmaxf(mx1, fmaxf(sacc[nt][2], sacc[nt][3]));
        }
        mx0 = fmaxf(mx0, __shfl_xor_sync(0xffffffffu, mx0, 1));
        mx0 = fmaxf(mx0, __shfl_xor_sync(0xffffffffu, mx0, 2));
        mx1 = fmaxf(mx1, __shfl_xor_sync(0xffffffffu, mx1, 1));
        mx1 = fmaxf(mx1, __shfl_xor_sync(0xffffffffu, mx1, 2));

        const float mn0 = fmaxf(m0, mx0), mn1 = fmaxf(m1, mx1);
        const float f0 = ex2(m0 - mn0), f1 = ex2(m1 - mn1);
        float ls0 = 0.f, ls1 = 0.f;
#pragma unroll
        for (int nt = 0; nt < 8; nt++) {
            const float p00 = ex2(sacc[nt][0] - mn0);
            const float p01 = ex2(sacc[nt][1] - mn0);
            const float p10 = ex2(sacc[nt][2] - mn1);
            const float p11 = ex2(sacc[nt][3] - mn1);
            ls0 += p00 + p01;
            ls1 += p10 + p11;
            *(uint32_t*)&Ps[(mb + g) * 72 + nt * 8 + 2 * t]     = pack_h2(p00, p01);
            *(uint32_t*)&Ps[(mb + g + 8) * 72 + nt * 8 + 2 * t] = pack_h2(p10, p11);
        }
        ls0 += __shfl_xor_sync(0xffffffffu, ls0, 1);
        ls0 += __shfl_xor_sync(0xffffffffu, ls0, 2);
        ls1 += __shfl_xor_sync(0xffffffffu, ls1, 1);
        ls1 += __shfl_xor_sync(0xffffffffu, ls1, 2);
        l0 = l0 * f0 + ls0;
        l1 = l1 * f1 + ls1;
        m0 = mn0; m1 = mn1;
#pragma unroll
        for (int nt = 0; nt < 8; nt++) {
            oacc[nt][0] *= f0; oacc[nt][1] *= f0;
            oacc[nt][2] *= f1; oacc[nt][3] *= f1;
        }
        __syncwarp();   // P rows are private to this warp

        // O += P @ V   (V^T tile: rows d, cols s)
#pragma unroll
        for (int ks = 0; ks < 4; ks++) {
            const int kb = ks * 16;
            uint32_t pa[4];
            ldsm4(pa[0], pa[1], pa[2], pa[3],
                  pmb + (uint32_t)((mb + a_r) * 72 + kb + a_c) * 2u);
            uint32_t bf[8][2];
#pragma unroll
            for (int p = 0; p < 4; p++)
                ldsm4(bf[2 * p][0], bf[2 * p][1], bf[2 * p + 1][0], bf[2 * p + 1][1],
                      vs_b + (uint32_t)((p * 16 + b_r) * 72 + kb + b_c) * 2u);
#pragma unroll
            for (int nt = 0; nt < 8; nt++)
                mma_f16(oacc[nt][0], oacc[nt][1], oacc[nt][2], oacc[nt][3],
                        pa[0], pa[1], pa[2], pa[3], bf[nt][0], bf[nt][1]);
        }
    }

    // epilogue -> g_att half [b][t][h][d]
    const float i0 = 1.0f / l0, i1 = 1.0f / l1;
    __half* O0 = (__half*)g_att + ((size_t)(b * TT + r0) * NH + h) * HD;
    __half* O1 = (__half*)g_att + ((size_t)(b * TT + r1) * NH + h) * HD;
#pragma unroll
    for (int nt = 0; nt < 8; nt++) {
        const int d = nt * 8 + 2 * t;
        *(uint32_t*)&O0[d] = pack_h2(oacc[nt][0] * i0, oacc[nt][1] * i0);
        *(uint32_t*)&O1[d] = pack_h2(oacc[nt][2] * i1, oacc[nt][3] * i1);
    }
}

// ---------------------------------------------------------------------------
// kernel_launch
// ---------------------------------------------------------------------------
extern "C" void kernel_launch(void* const* d_in, const int* in_sizes, int n_in,
                              void* d_out, int out_size)
{
    const float* x      = (const float*)d_in[0];
    const float* w_qkv  = (const float*)d_in[1];
    const float* b_qkv  = (const float*)d_in[2];
    const float* w_proj = (const float*)d_in[3];
    const float* b_proj = (const float*)d_in[4];
    float* out = (float*)d_out;

    const int M = BB * TT;  // 4096

    cudaFuncSetAttribute(mma_gemm<0>, cudaFuncAttributeMaxDynamicSharedMemorySize, GSMEM_BYTES);
    cudaFuncSetAttribute(mma_gemm<1>, cudaFuncAttributeMaxDynamicSharedMemorySize, GSMEM_BYTES);
    cudaFuncSetAttribute(flash_mma, cudaFuncAttributeMaxDynamicSharedMemorySize, FLASH_SMEM);

    // 0) prepass: round x; transpose+round both weights (one launch)
    round_x_k<<<512, 256>>>(x);
    transpose_both<<<dim3(128, 32), dim3(32, 8)>>>(w_qkv, w_proj);

    // 1) QKV projection (fp16 m16n8k16, 256x128 tile, 512 thr, 3-stage cp.async)
    mma_gemm<0><<<dim3(3 * DM / 128, M / 256), 512, GSMEM_BYTES>>>(b_qkv, nullptr, M, 3 * DM, DM);

    // 2) causal flash attention (fp16 MMA + ldmatrix, fp32 softmax) -> g_att
    flash_mma<<<dim3(TT / 128, NH, BB), 256, FLASH_SMEM>>>();

    // 3) output projection -> out (fp32)
    mma_gemm<1><<<dim3(DM / 128, M / 256), 512, GSMEM_BYTES>>>(b_proj, out, M, DM, DM);
}